// round 3
// baseline (speedup 1.0000x reference)
#include <cuda_runtime.h>

// HysteresisThresholding 2048x2048, gap-1/gap-2 8-connected hysteresis.
// Persistent kernel, 1 block/SM, band-local smem flood fill to fixed point,
// global passes exchange 4-row halos. Elementwise phases float4-vectorized
// with REDUX-packed bitmasks.

#define H_IMG 2048
#define W_IMG 2048
#define WX 64                    // 32-bit words per image row
#define QX 512                   // float4 quads per image row
#define N_WORDS (H_IMG * WX)
#define N_PIX (H_IMG * W_IMG)
#define N_QUAD (N_PIX / 4)
#define LOW_T 0.3f
#define HIGH_T 0.7f
#define MAX_PASS 256
#define MAX_ROWS 16
#define NT 1024

__device__ unsigned g_active[N_WORDS];
__device__ unsigned g_changed[MAX_PASS];
__device__ unsigned g_bar_count;
__device__ unsigned g_bar_gen;

__device__ __forceinline__ void grid_barrier(unsigned nblocks) {
    __syncthreads();
    if (threadIdx.x == 0) {
        __threadfence();
        volatile unsigned* genp = &g_bar_gen;
        unsigned gen = *genp;
        unsigned arr = atomicAdd(&g_bar_count, 1u);
        if (arr == nblocks - 1u) {
            atomicExch(&g_bar_count, 0u);
            __threadfence();
            atomicAdd(&g_bar_gen, 1u);
        } else {
            while (*genp == gen) { __nanosleep(32); }
        }
        __threadfence();
    }
    __syncthreads();
}

__global__ void __launch_bounds__(NT, 1)
hyst_kernel(const float* __restrict__ thin, float* __restrict__ out,
            int rows_per, unsigned nblocks) {
    __shared__ unsigned s_act[(MAX_ROWS + 4) * WX];  // band + 2-row halo each side
    __shared__ unsigned s_w1[MAX_ROWS * WX];
    __shared__ unsigned s_w2[MAX_ROWS * WX];

    const int tid  = threadIdx.x;
    const int lane = tid & 31;
    const int r0   = blockIdx.x * rows_per;
    const int nrows  = max(0, min(H_IMG - r0, rows_per));
    const int nwords = nrows * WX;
    const int nquads = nrows * QX;          // multiple of NT for our geometry

    const float4* thin4 = (const float4*)thin;
    float4* low4   = (float4*)out;
    float4* high4  = (float4*)(out + N_PIX);
    float4* final4 = (float4*)(out + 2 * N_PIX);

    const unsigned gsh   = (lane & 24u) >> 1;        // 4 * (group base / 2)... = 4*(lane&~7)/2
    const unsigned nsh   = (lane & 7u) * 4u;         // nibble shift within word
    const unsigned gmask = 0xFFu << (lane & 24u);    // 8-lane group member mask
    (void)gsh;

    // -------- init smem halos + pass flags --------
    for (int i = tid; i < (MAX_ROWS + 4) * WX; i += NT) s_act[i] = 0u;
    if (blockIdx.x == 0)
        for (int i = tid; i < MAX_PASS; i += NT) g_changed[i] = 0u;

    // -------- Phase 1: thresholds + bit-pack masks (float4) --------
    for (int i = tid; i < nquads; i += NT) {
        int qg = r0 * QX + i;
        float4 v = thin4[qg];

        float4 lo, hi;
        lo.x = (v.x < LOW_T)  ? 0.0f : v.x;  hi.x = (v.x < HIGH_T) ? 0.0f : v.x;
        lo.y = (v.y < LOW_T)  ? 0.0f : v.y;  hi.y = (v.y < HIGH_T) ? 0.0f : v.y;
        lo.z = (v.z < LOW_T)  ? 0.0f : v.z;  hi.z = (v.z < HIGH_T) ? 0.0f : v.z;
        lo.w = (v.w < LOW_T)  ? 0.0f : v.w;  hi.w = (v.w < HIGH_T) ? 0.0f : v.w;
        low4[qg]  = lo;
        high4[qg] = hi;

        unsigned nw = (v.x >= LOW_T ? 1u : 0u) | (v.y >= LOW_T ? 2u : 0u)
                    | (v.z >= LOW_T ? 4u : 0u) | (v.w >= LOW_T ? 8u : 0u);
        unsigned ns = (v.x >= HIGH_T ? 1u : 0u) | (v.y >= HIGH_T ? 2u : 0u)
                    | (v.z >= HIGH_T ? 4u : 0u) | (v.w >= HIGH_T ? 8u : 0u);
        unsigned wk = __reduce_or_sync(gmask, nw << nsh);
        unsigned ac = __reduce_or_sync(gmask, ns << nsh);

        if ((lane & 7) == 0) {
            int w  = i >> 3;                 // band-local word index
            int gw = r0 * WX + w;
            int r = gw >> 6, wx = gw & 63;
            unsigned t1c = (wx == 0) ? 0xFFFFFFFEu : (wx == WX - 1) ? 0x3FFFFFFFu : 0xFFFFFFFFu;
            unsigned t1r = (r >= 1 && r <= H_IMG - 3) ? 0xFFFFFFFFu : 0u;
            unsigned t2c = (wx == 0) ? 0xFFFFFFFCu : (wx == WX - 1) ? 0x1FFFFFFFu : 0xFFFFFFFFu;
            unsigned t2r = (r >= 2 && r <= H_IMG - 4) ? 0xFFFFFFFFu : 0u;
            s_w1[w] = wk & t1c & t1r;
            s_w2[w] = wk & t2c & t2r;
            s_act[((w >> 6) + 2) * WX + wx] = ac;
            __stcg(&g_active[gw], ac);
        }
    }

    grid_barrier(nblocks);

    // -------- Phase 2: flood fill, band-local convergence per pass --------
    for (int pass = 0; pass < MAX_PASS; pass++) {
        for (int i = tid; i < 4 * WX; i += NT) {
            int hr = i >> 6, wx = i & 63;
            int gr = (hr < 2) ? (r0 - 2 + hr) : (r0 + nrows + (hr - 2));
            int sr = (hr < 2) ? hr : (nrows + hr);
            unsigned v = 0u;
            if (gr >= 0 && gr < H_IMG) v = __ldcg(&g_active[gr * WX + wx]);
            s_act[sr * WX + wx] = v;
        }
        __syncthreads();

        bool band_changed = false;
        for (;;) {
            bool ch = false;
            if (tid < nwords) {
                int wx = tid & 63;
                int sr = (tid >> 6) + 2;
                unsigned c  = s_act[sr * WX + wx];
                unsigned w1 = s_w1[tid];
                unsigned w2 = s_w2[tid];
                unsigned todo = (w1 | w2) & ~c;
                if (todo) {
                    auto S = [&](int r_, int x_) -> unsigned {
                        return ((unsigned)x_ < (unsigned)WX) ? s_act[r_ * WX + x_] : 0u;
                    };
                    unsigned l  = S(sr, wx - 1),      rr = S(sr, wx + 1);
                    unsigned u1 = S(sr - 1, wx), u1l = S(sr - 1, wx - 1), u1r = S(sr - 1, wx + 1);
                    unsigned d1 = S(sr + 1, wx), d1l = S(sr + 1, wx - 1), d1r = S(sr + 1, wx + 1);
                    unsigned conn1 =
                          u1 | __funnelshift_l(u1l, u1, 1) | __funnelshift_r(u1, u1r, 1)
                        |      __funnelshift_l(l,   c,  1) | __funnelshift_r(c,  rr,  1)
                        | d1 | __funnelshift_l(d1l, d1, 1) | __funnelshift_r(d1, d1r, 1);
                    unsigned nw = c | (w1 & conn1);
                    if (w2 & ~nw) {
                        unsigned u2 = S(sr - 2, wx), u2l = S(sr - 2, wx - 1), u2r = S(sr - 2, wx + 1);
                        unsigned d2 = S(sr + 2, wx), d2l = S(sr + 2, wx - 1), d2r = S(sr + 2, wx + 1);
                        unsigned conn2 =
                              u2 | __funnelshift_l(u2l, u2, 2) | __funnelshift_r(u2, u2r, 2)
                            |      __funnelshift_l(l,   c,  2) | __funnelshift_r(c,  rr,  2)
                            | d2 | __funnelshift_l(d2l, d2, 2) | __funnelshift_r(d2, d2r, 2);
                        nw |= w2 & conn2;
                    }
                    #pragma unroll
                    for (int k = 0; k < 5; k++) {
                        unsigned sp = nw;
                        nw |= (w1 & ((sp << 1) | (sp >> 1)))
                            | (w2 & ((sp << 2) | (sp >> 2)));
                    }
                    if (nw != c) { s_act[sr * WX + wx] = nw; ch = true; }
                }
            }
            if (!__syncthreads_or(ch ? 1 : 0)) break;
            band_changed = true;
        }

        if (band_changed) {
            if (tid < nwords)
                __stcg(&g_active[r0 * WX + tid],
                       s_act[((tid >> 6) + 2) * WX + (tid & 63)]);
            if (tid == 0) __stcg(&g_changed[pass], 1u);
        }

        grid_barrier(nblocks);
        if (*(volatile unsigned*)&g_changed[pass] == 0u) break;
    }

    // -------- Phase 3: final output from converged smem band (float4) --------
    for (int i = tid; i < nquads; i += NT) {
        int qg = r0 * QX + i;
        int w  = i >> 3;
        unsigned word = s_act[((w >> 6) + 2) * WX + (w & 63)];
        unsigned bits = word >> nsh;
        float4 v = thin4[qg];
        float4 f;
        f.x = (bits & 1u) ? v.x : 0.0f;
        f.y = (bits & 2u) ? v.y : 0.0f;
        f.z = (bits & 4u) ? v.z : 0.0f;
        f.w = (bits & 8u) ? v.w : 0.0f;
        final4[qg] = f;
    }
}

extern "C" void kernel_launch(void* const* d_in, const int* in_sizes, int n_in,
                              void* d_out, int out_size) {
    const float* thin = (const float*)d_in[0];
    float* out = (float*)d_out;
    (void)in_sizes; (void)n_in; (void)out_size;

    int dev = 0;
    cudaGetDevice(&dev);
    int nsm = 0;
    cudaDeviceGetAttribute(&nsm, cudaDevAttrMultiProcessorCount, dev);
    if (nsm <= 0) nsm = 148;

    int rows_per = (H_IMG + nsm - 1) / nsm;
    if (rows_per > MAX_ROWS) rows_per = MAX_ROWS;
    unsigned grid = (unsigned)((H_IMG + rows_per - 1) / rows_per);

    hyst_kernel<<<grid, NT>>>(thin, out, rows_per, grid);
}

// round 4
// speedup vs baseline: 1.0348x; 1.0348x over previous
#include <cuda_runtime.h>

// HysteresisThresholding 2048x2048, gap-1/gap-2 8-connected hysteresis.
// Persistent kernel, 1 block/SM, band-local smem flood fill to fixed point.
// thin is staged into smem via cp.async (latency-hidden) and reused for both
// elementwise phases; phase 3 does zero global loads.

#define H_IMG 2048
#define W_IMG 2048
#define WX 64                    // 32-bit words per image row
#define QX 512                   // float4 quads per image row
#define N_WORDS (H_IMG * WX)
#define N_PIX (H_IMG * W_IMG)
#define LOW_T 0.3f
#define HIGH_T 0.7f
#define MAX_PASS 256
#define MAX_ROWS 16
#define NT 1024

// dynamic smem layout (in unsigned words)
#define SA_OFF 0                                   // s_act: (MAX_ROWS+4)*WX
#define W1_OFF ((MAX_ROWS + 4) * WX)               // s_w1: MAX_ROWS*WX
#define W2_OFF (W1_OFF + MAX_ROWS * WX)            // s_w2: MAX_ROWS*WX
#define TH_OFF (W2_OFF + MAX_ROWS * WX)            // s_thin: MAX_ROWS*QX float4
#define SMEM_WORDS (TH_OFF + MAX_ROWS * QX * 4)
#define SMEM_BYTES (SMEM_WORDS * 4)

__device__ unsigned g_active[N_WORDS];
__device__ unsigned g_changed[MAX_PASS];
__device__ unsigned g_bar_count;
__device__ unsigned g_bar_gen;

__device__ __forceinline__ void cp_async16(void* sdst, const void* gsrc) {
    unsigned saddr = (unsigned)__cvta_generic_to_shared(sdst);
    asm volatile("cp.async.cg.shared.global [%0], [%1], 16;\n"
                 :: "r"(saddr), "l"(gsrc) : "memory");
}

__device__ __forceinline__ void grid_barrier(unsigned nblocks) {
    __syncthreads();
    if (threadIdx.x == 0) {
        __threadfence();
        volatile unsigned* genp = &g_bar_gen;
        unsigned gen = *genp;
        unsigned arr = atomicAdd(&g_bar_count, 1u);
        if (arr == nblocks - 1u) {
            atomicExch(&g_bar_count, 0u);
            __threadfence();
            atomicAdd(&g_bar_gen, 1u);
        } else {
            while (*genp == gen) { __nanosleep(32); }
        }
        __threadfence();
    }
    __syncthreads();
}

__global__ void __launch_bounds__(NT, 1)
hyst_kernel(const float* __restrict__ thin, float* __restrict__ out,
            int rows_per, unsigned nblocks) {
    extern __shared__ unsigned smem[];
    unsigned* s_act = smem + SA_OFF;
    unsigned* s_w1  = smem + W1_OFF;
    unsigned* s_w2  = smem + W2_OFF;
    float4*   s_th  = (float4*)(smem + TH_OFF);

    const int tid  = threadIdx.x;
    const int lane = tid & 31;
    const int r0   = blockIdx.x * rows_per;
    const int nrows  = max(0, min(H_IMG - r0, rows_per));
    const int nwords = nrows * WX;
    const int nquads = nrows * QX;           // multiple of NT for our geometry

    const float4* thin4 = (const float4*)thin;
    float4* low4   = (float4*)out;
    float4* high4  = (float4*)(out + N_PIX);
    float4* final4 = (float4*)(out + 2 * N_PIX);

    const unsigned nsh   = (lane & 7u) * 4u;       // nibble shift within word
    const unsigned gmask = 0xFFu << (lane & 24u);  // 8-lane group mask

    // -------- stage thin into smem (latency-hidden) --------
    for (int j = tid; j < nquads; j += NT)
        cp_async16(&s_th[j], &thin4[r0 * QX + j]);
    asm volatile("cp.async.commit_group;\n");

    // init halos + pass flags while copies are in flight
    for (int i = tid; i < (MAX_ROWS + 4) * WX; i += NT) s_act[i] = 0u;
    if (blockIdx.x == 0)
        for (int i = tid; i < MAX_PASS; i += NT) g_changed[i] = 0u;

    asm volatile("cp.async.wait_group 0;\n" ::: "memory");
    __syncthreads();

    // -------- Phase 1: thresholds + bit-pack masks (from smem) --------
    for (int j = tid; j < nquads; j += NT) {
        float4 v = s_th[j];
        float4 lo, hi;
        lo.x = (v.x < LOW_T)  ? 0.0f : v.x;  hi.x = (v.x < HIGH_T) ? 0.0f : v.x;
        lo.y = (v.y < LOW_T)  ? 0.0f : v.y;  hi.y = (v.y < HIGH_T) ? 0.0f : v.y;
        lo.z = (v.z < LOW_T)  ? 0.0f : v.z;  hi.z = (v.z < HIGH_T) ? 0.0f : v.z;
        lo.w = (v.w < LOW_T)  ? 0.0f : v.w;  hi.w = (v.w < HIGH_T) ? 0.0f : v.w;
        int qg = r0 * QX + j;
        low4[qg]  = lo;
        high4[qg] = hi;

        unsigned nw = (v.x >= LOW_T ? 1u : 0u) | (v.y >= LOW_T ? 2u : 0u)
                    | (v.z >= LOW_T ? 4u : 0u) | (v.w >= LOW_T ? 8u : 0u);
        unsigned ns = (v.x >= HIGH_T ? 1u : 0u) | (v.y >= HIGH_T ? 2u : 0u)
                    | (v.z >= HIGH_T ? 4u : 0u) | (v.w >= HIGH_T ? 8u : 0u);
        unsigned wk = __reduce_or_sync(gmask, nw << nsh);
        unsigned ac = __reduce_or_sync(gmask, ns << nsh);

        if ((lane & 7) == 0) {
            int w  = j >> 3;
            int gw = r0 * WX + w;
            int r = gw >> 6, wx = gw & 63;
            unsigned t1c = (wx == 0) ? 0xFFFFFFFEu : (wx == WX - 1) ? 0x3FFFFFFFu : 0xFFFFFFFFu;
            unsigned t1r = (r >= 1 && r <= H_IMG - 3) ? 0xFFFFFFFFu : 0u;
            unsigned t2c = (wx == 0) ? 0xFFFFFFFCu : (wx == WX - 1) ? 0x1FFFFFFFu : 0xFFFFFFFFu;
            unsigned t2r = (r >= 2 && r <= H_IMG - 4) ? 0xFFFFFFFFu : 0u;
            s_w1[w] = wk & t1c & t1r;
            s_w2[w] = wk & t2c & t2r;
            s_act[((w >> 6) + 2) * WX + wx] = ac;
            __stcg(&g_active[gw], ac);
        }
    }

    grid_barrier(nblocks);

    // -------- Phase 2: flood fill, band-local convergence per pass --------
    for (int pass = 0; pass < MAX_PASS; pass++) {
        for (int i = tid; i < 4 * WX; i += NT) {
            int hr = i >> 6, wx = i & 63;
            int gr = (hr < 2) ? (r0 - 2 + hr) : (r0 + nrows + (hr - 2));
            int sr = (hr < 2) ? hr : (nrows + hr);
            unsigned v = 0u;
            if (gr >= 0 && gr < H_IMG) v = __ldcg(&g_active[gr * WX + wx]);
            s_act[sr * WX + wx] = v;
        }
        __syncthreads();

        bool band_changed = false;
        for (;;) {
            bool ch = false;
            if (tid < nwords) {
                int wx = tid & 63;
                int sr = (tid >> 6) + 2;
                unsigned c  = s_act[sr * WX + wx];
                unsigned w1 = s_w1[tid];
                unsigned w2 = s_w2[tid];
                unsigned todo = (w1 | w2) & ~c;
                if (todo) {
                    auto S = [&](int r_, int x_) -> unsigned {
                        return ((unsigned)x_ < (unsigned)WX) ? s_act[r_ * WX + x_] : 0u;
                    };
                    unsigned l  = S(sr, wx - 1),      rr = S(sr, wx + 1);
                    unsigned u1 = S(sr - 1, wx), u1l = S(sr - 1, wx - 1), u1r = S(sr - 1, wx + 1);
                    unsigned d1 = S(sr + 1, wx), d1l = S(sr + 1, wx - 1), d1r = S(sr + 1, wx + 1);
                    unsigned conn1 =
                          u1 | __funnelshift_l(u1l, u1, 1) | __funnelshift_r(u1, u1r, 1)
                        |      __funnelshift_l(l,   c,  1) | __funnelshift_r(c,  rr,  1)
                        | d1 | __funnelshift_l(d1l, d1, 1) | __funnelshift_r(d1, d1r, 1);
                    unsigned nw = c | (w1 & conn1);
                    if (w2 & ~nw) {
                        unsigned u2 = S(sr - 2, wx), u2l = S(sr - 2, wx - 1), u2r = S(sr - 2, wx + 1);
                        unsigned d2 = S(sr + 2, wx), d2l = S(sr + 2, wx - 1), d2r = S(sr + 2, wx + 1);
                        unsigned conn2 =
                              u2 | __funnelshift_l(u2l, u2, 2) | __funnelshift_r(u2, u2r, 2)
                            |      __funnelshift_l(l,   c,  2) | __funnelshift_r(c,  rr,  2)
                            | d2 | __funnelshift_l(d2l, d2, 2) | __funnelshift_r(d2, d2r, 2);
                        nw |= w2 & conn2;
                    }
                    #pragma unroll
                    for (int k = 0; k < 5; k++) {
                        unsigned sp = nw;
                        nw |= (w1 & ((sp << 1) | (sp >> 1)))
                            | (w2 & ((sp << 2) | (sp >> 2)));
                    }
                    if (nw != c) { s_act[sr * WX + wx] = nw; ch = true; }
                }
            }
            if (!__syncthreads_or(ch ? 1 : 0)) break;
            band_changed = true;
        }

        if (band_changed) {
            if (tid < nwords)
                __stcg(&g_active[r0 * WX + tid],
                       s_act[((tid >> 6) + 2) * WX + (tid & 63)]);
            if (tid == 0) __stcg(&g_changed[pass], 1u);
        }

        grid_barrier(nblocks);
        if (*(volatile unsigned*)&g_changed[pass] == 0u) break;
    }

    // -------- Phase 3: final output, zero global loads --------
    for (int j = tid; j < nquads; j += NT) {
        int w = j >> 3;
        unsigned word = s_act[((w >> 6) + 2) * WX + (w & 63)];
        unsigned bits = word >> nsh;
        float4 v = s_th[j];
        float4 f;
        f.x = (bits & 1u) ? v.x : 0.0f;
        f.y = (bits & 2u) ? v.y : 0.0f;
        f.z = (bits & 4u) ? v.z : 0.0f;
        f.w = (bits & 8u) ? v.w : 0.0f;
        final4[r0 * QX + j] = f;
    }
}

extern "C" void kernel_launch(void* const* d_in, const int* in_sizes, int n_in,
                              void* d_out, int out_size) {
    const float* thin = (const float*)d_in[0];
    float* out = (float*)d_out;
    (void)in_sizes; (void)n_in; (void)out_size;

    int dev = 0;
    cudaGetDevice(&dev);
    int nsm = 0;
    cudaDeviceGetAttribute(&nsm, cudaDevAttrMultiProcessorCount, dev);
    if (nsm <= 0) nsm = 148;

    static int attr_done = 0;
    if (!attr_done) {
        cudaFuncSetAttribute(hyst_kernel,
                             cudaFuncAttributeMaxDynamicSharedMemorySize, SMEM_BYTES);
        attr_done = 1;
    }

    int rows_per = (H_IMG + nsm - 1) / nsm;
    if (rows_per > MAX_ROWS) rows_per = MAX_ROWS;
    unsigned grid = (unsigned)((H_IMG + rows_per - 1) / rows_per);

    hyst_kernel<<<grid, NT, SMEM_BYTES>>>(thin, out, rows_per, grid);
}